// round 12
// baseline (speedup 1.0000x reference)
#include <cuda_runtime.h>
#include <cuda_fp16.h>
#include <cstdint>
#include <math.h>

#define MEM   1024
#define LSEQ  512
#define BATCH 128
#define INDIM 512
#define MROWS (BATCH * LSEQ)   /* 65536 */
#define NCOLS (2 * MEM)        /* 2048  */

/* ---- static scratch (no runtime allocation) ------------------------------ */
__device__ __align__(128) __half g_Ah[(size_t)MROWS * INDIM];
__device__ __align__(128) __half g_Wh[(size_t)NCOLS * INDIM];
__device__ __align__(128) __half g_sb[(size_t)MROWS * MEM];   /* soma_bias fp16 */
__device__ __align__(128) __half g_io[(size_t)MROWS * MEM];   /* io half  fp16 */

/* ------------------------------ PTX helpers ------------------------------ */
__device__ __forceinline__ uint32_t smem_u32(const void* p) {
    uint32_t a;
    asm("{ .reg .u64 t; cvta.to.shared.u64 t, %1; cvt.u32.u64 %0, t; }"
        : "=r"(a) : "l"(p));
    return a;
}
__device__ __forceinline__ void cp16(uint32_t dst, const void* src) {
    asm volatile("cp.async.cg.shared.global [%0], [%1], 16;" :: "r"(dst), "l"(src));
}
#define CP_COMMIT() asm volatile("cp.async.commit_group;" ::: "memory")
#define CP_WAIT1()  asm volatile("cp.async.wait_group 1;" ::: "memory")

__device__ __forceinline__ void ldsm4(uint32_t* r, uint32_t addr) {
    asm volatile("ldmatrix.sync.aligned.m8n8.x4.shared.b16 {%0,%1,%2,%3}, [%4];"
                 : "=r"(r[0]), "=r"(r[1]), "=r"(r[2]), "=r"(r[3]) : "r"(addr));
}
__device__ __forceinline__ void mma16816(float* c, const uint32_t* a,
                                         const uint32_t b0, const uint32_t b1) {
    asm volatile(
        "mma.sync.aligned.m16n8k16.row.col.f32.f16.f16.f32 "
        "{%0,%1,%2,%3}, {%4,%5,%6,%7}, {%8,%9}, {%0,%1,%2,%3};"
        : "+f"(c[0]), "+f"(c[1]), "+f"(c[2]), "+f"(c[3])
        : "r"(a[0]), "r"(a[1]), "r"(a[2]), "r"(a[3]), "r"(b0), "r"(b1));
}

/* --------------- GEMM via mma.sync, single-pass fp16 --------------------- */
/* CTA 128x128, warp 32x64 (4m x 2n), BK=64, 8 k-chunks, 2 CTAs/SM          */
/* smem tile: 128 rows x 128B, XOR-16B swizzle: chunk' = chunk ^ (row & 7)   */
#define ROWB    128
#define TILE_B  (128 * ROWB)             /* 16384                            */
#define STAGE_B (2 * TILE_B)             /* A | B = 32768                    */
#define NSTG    3
#define BIAS_OFF (NSTG * STAGE_B)        /* 98304 */
#define SMEM_SZ (BIAS_OFF + 512)
#define NITER   8

__global__ void __launch_bounds__(256, 2) gemm_mma(const float* __restrict__ bias)
{
    extern __shared__ char smem[];
    const uint32_t sb0 = smem_u32(smem);
    const int tid = threadIdx.x, wid = tid >> 5, lane = tid & 31;
    const int bn = blockIdx.x * 128, bm = blockIdx.y * 128;

    if (tid < 128) ((float*)(smem + BIAS_OFF))[tid] = bias[bn + tid];

    float acc[2][8][4];
#pragma unroll
    for (int i = 0; i < 2; i++)
#pragma unroll
        for (int j = 0; j < 8; j++)
#pragma unroll
            for (int q = 0; q < 4; q++) acc[i][j][q] = 0.0f;

    /* per k-chunk: load A|B tiles (128x64 fp16 each), 8 cp16/thread */
    auto load_stage = [&](int c, int s) {
        const int ko = c * 64;
        const __half* srcA = g_Ah + (size_t)bm * INDIM + ko;
        const __half* srcB = g_Wh + (size_t)bn * INDIM + ko;
        const uint32_t dst = sb0 + s * STAGE_B;
#pragma unroll
        for (int j = 0; j < 8; j++) {
            const int id = tid + 256 * j;          /* 0..2047 */
            const int t = id >> 10;                /* 0: A, 1: B */
            const int w = id & 1023;
            const int row = w >> 3, un = w & 7;
            const int sw = un ^ (row & 7);
            const __half* src = t ? srcB : srcA;
            cp16(dst + t * TILE_B + row * ROWB + sw * 16,
                 src + (size_t)row * INDIM + un * 8);
        }
    };

    load_stage(0, 0); CP_COMMIT();
    load_stage(1, 1); CP_COMMIT();

    const int wm = (wid & 3) * 32;     /* 4 warps down m   */
    const int wn = (wid >> 2) * 64;    /* 2 warps across n */
    const int lr = lane & 15;          /* row within 16    */
    const int cb = lane >> 4;          /* 16B chunk base   */
    const int lx = lr & 7;             /* swizzle key      */

    auto fragaddr = [&](uint32_t tilebase, int rowoff, int ks) -> uint32_t {
        return tilebase + (rowoff + lr) * ROWB + (((cb + 2 * ks) ^ lx) * 16);
    };

    for (int it = 0; it < NITER; it++) {
        const int s = it % NSTG;
        CP_WAIT1();
        __syncthreads();

        const uint32_t aB = sb0 + s * STAGE_B;
        const uint32_t bB = aB + TILE_B;

#pragma unroll
        for (int ks = 0; ks < 4; ks++) {
            uint32_t a[2][4], bq[4][4];
            ldsm4(a[0], fragaddr(aB, wm, ks));
            ldsm4(a[1], fragaddr(aB, wm + 16, ks));
#pragma unroll
            for (int pr = 0; pr < 4; pr++)
                ldsm4(bq[pr], fragaddr(bB, wn + pr * 16, ks));
#pragma unroll
            for (int mt = 0; mt < 2; mt++)
#pragma unroll
                for (int nt = 0; nt < 8; nt++)
                    mma16816(acc[mt][nt], a[mt],
                             bq[nt >> 1][nt & 1], bq[nt >> 1][(nt & 1) + 2]);
        }
        if (it + 2 < NITER) load_stage(it + 2, (it + 2) % NSTG);
        CP_COMMIT();                    /* unconditional: group numbering */
    }
    __syncthreads();

    /* epilogue: +bias; sb half -> tanh -> fp16; io half -> fp16 */
    const float* bsh = (const float*)(smem + BIAS_OFF);
    const bool is_sb = (bn < MEM);
    __half* ob = is_sb ? g_sb : g_io;
    const int cs = is_sb ? bn : (bn - MEM);

#pragma unroll
    for (int mt = 0; mt < 2; mt++) {
        const int r0 = bm + wm + mt * 16 + (lane >> 2);
#pragma unroll
        for (int nt = 0; nt < 8; nt++) {
            const int col = wn + nt * 8 + (lane & 3) * 2;
            const float b0 = bsh[col], b1 = bsh[col + 1];
            float2 v0, v1;
            v0.x = acc[mt][nt][0] + b0; v0.y = acc[mt][nt][1] + b1;
            v1.x = acc[mt][nt][2] + b0; v1.y = acc[mt][nt][3] + b1;
            if (is_sb) {
                v0.x = 5.0f * tanhf(v0.x * 0.2f); v0.y = 5.0f * tanhf(v0.y * 0.2f);
                v1.x = 5.0f * tanhf(v1.x * 0.2f); v1.y = 5.0f * tanhf(v1.y * 0.2f);
            }
            *(__half2*)&ob[(size_t)r0 * MEM + cs + col] = __float22half2_rn(v0);
            *(__half2*)&ob[(size_t)(r0 + 8) * MEM + cs + col] = __float22half2_rn(v1);
        }
    }
}

/* --------------- fp32 -> fp16 convert (u and W in one launch) ------------ */
#define NA (MROWS * INDIM / 4)   /* 8388608 float4 elems of u */
#define NW (NCOLS * INDIM / 4)   /* 262144  float4 elems of W */

__device__ __forceinline__ void cvt4(const float4 v, __half2* dst2, size_t i) {
    dst2[2 * i]     = __floats2half2_rn(v.x, v.y);
    dst2[2 * i + 1] = __floats2half2_rn(v.z, v.w);
}

__global__ void __launch_bounds__(256) cvt_all(const float* __restrict__ u,
                                               const float* __restrict__ W) {
    const size_t i = (size_t)blockIdx.x * 256 + threadIdx.x;
    if (i < NA) {
        float4 v = ((const float4*)u)[i];
        cvt4(v, (__half2*)g_Ah, i);
    } else {
        const size_t j = i - NA;
        float4 v = ((const float4*)W)[j];
        cvt4(v, (__half2*)g_Wh, j);
    }
}

/* --------------- sequential scan (fp16 in, fp32 out, pf=4) --------------- */
__device__ __forceinline__ void step1(float& hf, float& hs, float io, float sb) {
    const float d = hs + 0.4f;
    const float hfn = tanhf(io + 4.0f * hf - 7.0f * d * d + sb);
    const float e = __expf(-10.0f * (hf - 0.5f));
    const float eps = 0.9f + __fdividef(0.9f, 1.0f + e);
    hs += eps * (hf - hs);
    hf = hfn;
}

__global__ void __launch_bounds__(128) scan2(const float* __restrict__ h0,
                                             float* __restrict__ out) {
    const int g = blockIdx.x * 128 + threadIdx.x;  /* 0..65535 */
    const int b = g >> 9;
    const int m2 = g & 511;                        /* half2/float2 column */

    const float2* h02 = (const float2*)h0;
    float2 hf = h02[(size_t)b * 512 + m2];
    float2 hs = h02[(size_t)BATCH * 512 + (size_t)b * 512 + m2];

    float2* out2 = (float2*)out;
    const __half2* io2 = (const __half2*)g_io;
    const __half2* sb2 = (const __half2*)g_sb;
    size_t idx = ((size_t)b * LSEQ) * 512 + m2;

    __half2 io[4], sb[4];
#pragma unroll
    for (int k = 0; k < 4; k++) {
        io[k] = io2[idx + 512 * k];
        sb[k] = sb2[idx + 512 * k];
    }

#pragma unroll 1
    for (int t = 0; t < LSEQ; t += 4) {
        __half2 nio[4], nsb[4];
        if (t + 4 < LSEQ) {
#pragma unroll
            for (int k = 0; k < 4; k++) {
                nio[k] = io2[idx + 2048 + 512 * k];
                nsb[k] = sb2[idx + 2048 + 512 * k];
            }
        }
#pragma unroll
        for (int k = 0; k < 4; k++) {
            const float2 iof = __half22float2(io[k]);
            const float2 sbf = __half22float2(sb[k]);
            step1(hf.x, hs.x, iof.x, sbf.x);
            step1(hf.y, hs.y, iof.y, sbf.y);
            out2[idx] = hf; idx += 512;
        }
        if (t + 4 < LSEQ) {
#pragma unroll
            for (int k = 0; k < 4; k++) { io[k] = nio[k]; sb[k] = nsb[k]; }
        }
    }
    out2[(size_t)MROWS * 512 + (size_t)b * 512 + m2] = hf;  /* hf_last */
}

/* ------------------------------- launch ---------------------------------- */
extern "C" void kernel_launch(void* const* d_in, const int* in_sizes, int n_in,
                              void* d_out, int out_size)
{
    const float* u    = (const float*)d_in[0];  /* [128,512,512] */
    const float* h0   = (const float*)d_in[1];  /* [2,128,1024]  */
    const float* W    = (const float*)d_in[2];  /* [2048,512]    */
    const float* bias = (const float*)d_in[3];  /* [2048]        */
    float* out = (float*)d_out;

    cudaFuncSetAttribute(gemm_mma, cudaFuncAttributeMaxDynamicSharedMemorySize, SMEM_SZ);

    cvt_all<<<(NA + NW) / 256, 256>>>(u, W);
    gemm_mma<<<dim3(NCOLS / 128, MROWS / 128), 256, SMEM_SZ>>>(bias);
    scan2<<<(BATCH * MEM / 2) / 128, 128>>>(h0, out);
}

// round 13
// speedup vs baseline: 1.0033x; 1.0033x over previous
#include <cuda_runtime.h>
#include <cuda_fp16.h>
#include <cstdint>
#include <math.h>

#define MEM   1024
#define LSEQ  512
#define BATCH 128
#define INDIM 512
#define MROWS (BATCH * LSEQ)   /* 65536 */
#define NCOLS (2 * MEM)        /* 2048  */

/* ---- static scratch (no runtime allocation) ------------------------------ */
__device__ __align__(128) __half g_Ah[(size_t)MROWS * INDIM];
__device__ __align__(128) __half g_Wh[(size_t)NCOLS * INDIM];
__device__ __align__(128) __half g_sb[(size_t)MROWS * MEM];   /* soma_bias fp16 */
__device__ __align__(128) __half g_io[(size_t)MROWS * MEM];   /* io half  fp16 */

/* ------------------------------ PTX helpers ------------------------------ */
__device__ __forceinline__ uint32_t smem_u32(const void* p) {
    uint32_t a;
    asm("{ .reg .u64 t; cvta.to.shared.u64 t, %1; cvt.u32.u64 %0, t; }"
        : "=r"(a) : "l"(p));
    return a;
}
__device__ __forceinline__ void cp16(uint32_t dst, const void* src) {
    asm volatile("cp.async.cg.shared.global [%0], [%1], 16;" :: "r"(dst), "l"(src));
}
#define CP_COMMIT() asm volatile("cp.async.commit_group;" ::: "memory")
#define CP_WAIT1()  asm volatile("cp.async.wait_group 1;" ::: "memory")

__device__ __forceinline__ void ldsm4(uint32_t* r, uint32_t addr) {
    asm volatile("ldmatrix.sync.aligned.m8n8.x4.shared.b16 {%0,%1,%2,%3}, [%4];"
                 : "=r"(r[0]), "=r"(r[1]), "=r"(r[2]), "=r"(r[3]) : "r"(addr));
}
__device__ __forceinline__ void mma16816(float* c, const uint32_t* a,
                                         const uint32_t b0, const uint32_t b1) {
    asm volatile(
        "mma.sync.aligned.m16n8k16.row.col.f32.f16.f16.f32 "
        "{%0,%1,%2,%3}, {%4,%5,%6,%7}, {%8,%9}, {%0,%1,%2,%3};"
        : "+f"(c[0]), "+f"(c[1]), "+f"(c[2]), "+f"(c[3])
        : "r"(a[0]), "r"(a[1]), "r"(a[2]), "r"(a[3]), "r"(b0), "r"(b1));
}

/* --------------- GEMM via mma.sync, single-pass fp16 --------------------- */
/* CTA 128x128, warp 32x64 (4m x 2n), BK=64, 8 k-chunks, 2 CTAs/SM          */
/* smem tile: 128 rows x 128B, XOR-16B swizzle: chunk' = chunk ^ (row & 7)   */
#define ROWB    128
#define TILE_B  (128 * ROWB)             /* 16384                            */
#define STAGE_B (2 * TILE_B)             /* A | B = 32768                    */
#define NSTG    3
#define BIAS_OFF (NSTG * STAGE_B)        /* 98304 */
#define SMEM_SZ (BIAS_OFF + 512)
#define NITER   8
/* epilogue staging: 128 rows x 256B data, 272B row stride (bank-safe)       */
#define EROWB   272

__global__ void __launch_bounds__(256, 2) gemm_mma(const float* __restrict__ bias)
{
    extern __shared__ char smem[];
    const uint32_t sb0 = smem_u32(smem);
    const int tid = threadIdx.x, wid = tid >> 5, lane = tid & 31;
    const int bn = blockIdx.x * 128, bm = blockIdx.y * 128;

    if (tid < 128) ((float*)(smem + BIAS_OFF))[tid] = bias[bn + tid];

    float acc[2][8][4];
#pragma unroll
    for (int i = 0; i < 2; i++)
#pragma unroll
        for (int j = 0; j < 8; j++)
#pragma unroll
            for (int q = 0; q < 4; q++) acc[i][j][q] = 0.0f;

    /* per k-chunk: load A|B tiles (128x64 fp16 each), 8 cp16/thread */
    auto load_stage = [&](int c, int s) {
        const int ko = c * 64;
        const __half* srcA = g_Ah + (size_t)bm * INDIM + ko;
        const __half* srcB = g_Wh + (size_t)bn * INDIM + ko;
        const uint32_t dst = sb0 + s * STAGE_B;
#pragma unroll
        for (int j = 0; j < 8; j++) {
            const int id = tid + 256 * j;          /* 0..2047 */
            const int t = id >> 10;                /* 0: A, 1: B */
            const int w = id & 1023;
            const int row = w >> 3, un = w & 7;
            const int sw = un ^ (row & 7);
            const __half* src = t ? srcB : srcA;
            cp16(dst + t * TILE_B + row * ROWB + sw * 16,
                 src + (size_t)row * INDIM + un * 8);
        }
    };

    load_stage(0, 0); CP_COMMIT();
    load_stage(1, 1); CP_COMMIT();

    const int wm = (wid & 3) * 32;     /* 4 warps down m   */
    const int wn = (wid >> 2) * 64;    /* 2 warps across n */
    const int lr = lane & 15;          /* row within 16    */
    const int cb = lane >> 4;          /* 16B chunk base   */
    const int lx = lr & 7;             /* swizzle key      */

    auto fragaddr = [&](uint32_t tilebase, int rowoff, int ks) -> uint32_t {
        return tilebase + (rowoff + lr) * ROWB + (((cb + 2 * ks) ^ lx) * 16);
    };

    for (int it = 0; it < NITER; it++) {
        const int s = it % NSTG;
        CP_WAIT1();
        __syncthreads();

        const uint32_t aB = sb0 + s * STAGE_B;
        const uint32_t bB = aB + TILE_B;

#pragma unroll
        for (int ks = 0; ks < 4; ks++) {
            uint32_t a[2][4], bq[4][4];
            ldsm4(a[0], fragaddr(aB, wm, ks));
            ldsm4(a[1], fragaddr(aB, wm + 16, ks));
#pragma unroll
            for (int pr = 0; pr < 4; pr++)
                ldsm4(bq[pr], fragaddr(bB, wn + pr * 16, ks));
#pragma unroll
            for (int mt = 0; mt < 2; mt++)
#pragma unroll
                for (int nt = 0; nt < 8; nt++)
                    mma16816(acc[mt][nt], a[mt],
                             bq[nt >> 1][nt & 1], bq[nt >> 1][(nt & 1) + 2]);
        }
        if (it + 2 < NITER) load_stage(it + 2, (it + 2) % NSTG);
        CP_COMMIT();                    /* unconditional: group numbering */
    }
    __syncthreads();

    /* ---- epilogue: +bias, optional tanh, fp16 via SMEM staging ----------
       phase 1: half2 STS into 272B-stride staging (bank-conflict-free)
       phase 2: 16B LDS + STG.128, lanes 0-15 = one contiguous 256B row     */
    const float* bsh = (const float*)(smem + BIAS_OFF);
    const bool is_sb = (bn < MEM);
    __half* ob = is_sb ? g_sb : g_io;
    const int cs = is_sb ? bn : (bn - MEM);

#pragma unroll
    for (int mt = 0; mt < 2; mt++) {
        const int r0 = wm + mt * 16 + (lane >> 2);
#pragma unroll
        for (int nt = 0; nt < 8; nt++) {
            const int col = wn + nt * 8 + (lane & 3) * 2;
            const float b0 = bsh[col], b1 = bsh[col + 1];
            float2 v0, v1;
            v0.x = acc[mt][nt][0] + b0; v0.y = acc[mt][nt][1] + b1;
            v1.x = acc[mt][nt][2] + b0; v1.y = acc[mt][nt][3] + b1;
            if (is_sb) {
                v0.x = 5.0f * tanhf(v0.x * 0.2f); v0.y = 5.0f * tanhf(v0.y * 0.2f);
                v1.x = 5.0f * tanhf(v1.x * 0.2f); v1.y = 5.0f * tanhf(v1.y * 0.2f);
            }
            *(__half2*)(smem + r0 * EROWB + col * 2)       = __float22half2_rn(v0);
            *(__half2*)(smem + (r0 + 8) * EROWB + col * 2) = __float22half2_rn(v1);
        }
    }
    __syncthreads();

#pragma unroll
    for (int k = 0; k < 8; k++) {
        const int gchunk = k * 256 + tid;      /* 0..2047 */
        const int row = gchunk >> 4;           /* 16 chunks (256B) per row */
        const int c16 = gchunk & 15;
        uint4 v = *(const uint4*)(smem + row * EROWB + c16 * 16);
        *(uint4*)&ob[(size_t)(bm + row) * MEM + cs + c16 * 8] = v;
    }
}

/* --------------- fp32 -> fp16 convert (u and W in one launch) ------------ */
#define NA (MROWS * INDIM / 4)   /* 8388608 float4 elems of u */
#define NW (NCOLS * INDIM / 4)   /* 262144  float4 elems of W */

__device__ __forceinline__ void cvt4(const float4 v, __half2* dst2, size_t i) {
    dst2[2 * i]     = __floats2half2_rn(v.x, v.y);
    dst2[2 * i + 1] = __floats2half2_rn(v.z, v.w);
}

__global__ void __launch_bounds__(256) cvt_all(const float* __restrict__ u,
                                               const float* __restrict__ W) {
    const size_t i = (size_t)blockIdx.x * 256 + threadIdx.x;
    if (i < NA) {
        float4 v = ((const float4*)u)[i];
        cvt4(v, (__half2*)g_Ah, i);
    } else {
        const size_t j = i - NA;
        float4 v = ((const float4*)W)[j];
        cvt4(v, (__half2*)g_Wh, j);
    }
}

/* --------------- sequential scan (fp16 in, fp32 out, pf=4) --------------- */
__device__ __forceinline__ void step1(float& hf, float& hs, float io, float sb) {
    const float d = hs + 0.4f;
    const float hfn = tanhf(io + 4.0f * hf - 7.0f * d * d + sb);
    const float e = __expf(-10.0f * (hf - 0.5f));
    const float eps = 0.9f + __fdividef(0.9f, 1.0f + e);
    hs += eps * (hf - hs);
    hf = hfn;
}

__global__ void __launch_bounds__(128) scan2(const float* __restrict__ h0,
                                             float* __restrict__ out) {
    const int g = blockIdx.x * 128 + threadIdx.x;  /* 0..65535 */
    const int b = g >> 9;
    const int m2 = g & 511;                        /* half2/float2 column */

    const float2* h02 = (const float2*)h0;
    float2 hf = h02[(size_t)b * 512 + m2];
    float2 hs = h02[(size_t)BATCH * 512 + (size_t)b * 512 + m2];

    float2* out2 = (float2*)out;
    const __half2* io2 = (const __half2*)g_io;
    const __half2* sb2 = (const __half2*)g_sb;
    size_t idx = ((size_t)b * LSEQ) * 512 + m2;

    __half2 io[4], sb[4];
#pragma unroll
    for (int k = 0; k < 4; k++) {
        io[k] = io2[idx + 512 * k];
        sb[k] = sb2[idx + 512 * k];
    }

#pragma unroll 1
    for (int t = 0; t < LSEQ; t += 4) {
        __half2 nio[4], nsb[4];
        if (t + 4 < LSEQ) {
#pragma unroll
            for (int k = 0; k < 4; k++) {
                nio[k] = io2[idx + 2048 + 512 * k];
                nsb[k] = sb2[idx + 2048 + 512 * k];
            }
        }
#pragma unroll
        for (int k = 0; k < 4; k++) {
            const float2 iof = __half22float2(io[k]);
            const float2 sbf = __half22float2(sb[k]);
            step1(hf.x, hs.x, iof.x, sbf.x);
            step1(hf.y, hs.y, iof.y, sbf.y);
            out2[idx] = hf; idx += 512;
        }
        if (t + 4 < LSEQ) {
#pragma unroll
            for (int k = 0; k < 4; k++) { io[k] = nio[k]; sb[k] = nsb[k]; }
        }
    }
    out2[(size_t)MROWS * 512 + (size_t)b * 512 + m2] = hf;  /* hf_last */
}

/* ------------------------------- launch ---------------------------------- */
extern "C" void kernel_launch(void* const* d_in, const int* in_sizes, int n_in,
                              void* d_out, int out_size)
{
    const float* u    = (const float*)d_in[0];  /* [128,512,512] */
    const float* h0   = (const float*)d_in[1];  /* [2,128,1024]  */
    const float* W    = (const float*)d_in[2];  /* [2048,512]    */
    const float* bias = (const float*)d_in[3];  /* [2048]        */
    float* out = (float*)d_out;

    cudaFuncSetAttribute(gemm_mma, cudaFuncAttributeMaxDynamicSharedMemorySize, SMEM_SZ);

    cvt_all<<<(NA + NW) / 256, 256>>>(u, W);
    gemm_mma<<<dim3(NCOLS / 128, MROWS / 128), 256, SMEM_SZ>>>(bias);
    scan2<<<(BATCH * MEM / 2) / 128, 128>>>(h0, out);
}

// round 14
// speedup vs baseline: 1.0164x; 1.0131x over previous
#include <cuda_runtime.h>
#include <cuda_fp16.h>
#include <cstdint>
#include <math.h>

#define MEM   1024
#define LSEQ  512
#define BATCH 128
#define INDIM 512
#define MROWS (BATCH * LSEQ)   /* 65536 */
#define NCOLS (2 * MEM)        /* 2048  */

/* ---- static scratch (no runtime allocation) ------------------------------ */
__device__ __align__(128) __half g_Ah[(size_t)MROWS * INDIM];
__device__ __align__(128) __half g_Wh[(size_t)NCOLS * INDIM];
__device__ __align__(128) float  g_sb[(size_t)MROWS * MEM];   /* soma_bias */

/* ------------------------------ PTX helpers ------------------------------ */
__device__ __forceinline__ uint32_t smem_u32(const void* p) {
    uint32_t a;
    asm("{ .reg .u64 t; cvta.to.shared.u64 t, %1; cvt.u32.u64 %0, t; }"
        : "=r"(a) : "l"(p));
    return a;
}
__device__ __forceinline__ void cp16(uint32_t dst, const void* src) {
    asm volatile("cp.async.cg.shared.global [%0], [%1], 16;" :: "r"(dst), "l"(src));
}
#define CP_COMMIT() asm volatile("cp.async.commit_group;" ::: "memory")
#define CP_WAIT1()  asm volatile("cp.async.wait_group 1;" ::: "memory")

__device__ __forceinline__ void ldsm4(uint32_t* r, uint32_t addr) {
    asm volatile("ldmatrix.sync.aligned.m8n8.x4.shared.b16 {%0,%1,%2,%3}, [%4];"
                 : "=r"(r[0]), "=r"(r[1]), "=r"(r[2]), "=r"(r[3]) : "r"(addr));
}
__device__ __forceinline__ void mma16816(float* c, const uint32_t* a,
                                         const uint32_t b0, const uint32_t b1) {
    asm volatile(
        "mma.sync.aligned.m16n8k16.row.col.f32.f16.f16.f32 "
        "{%0,%1,%2,%3}, {%4,%5,%6,%7}, {%8,%9}, {%0,%1,%2,%3};"
        : "+f"(c[0]), "+f"(c[1]), "+f"(c[2]), "+f"(c[3])
        : "r"(a[0]), "r"(a[1]), "r"(a[2]), "r"(a[3]), "r"(b0), "r"(b1));
}

/* --------------- GEMM via mma.sync, single-pass fp16 --------------------- */
/* CTA 128x128, warp 32x64 (4m x 2n), BK=64, 8 k-chunks, 2 CTAs/SM          */
/* smem tile: 128 rows x 128B, XOR-16B swizzle: chunk' = chunk ^ (row & 7)   */
#define ROWB    128
#define TILE_B  (128 * ROWB)             /* 16384                            */
#define STAGE_B (2 * TILE_B)             /* A | B = 32768                    */
#define NSTG    3
#define BIAS_OFF (NSTG * STAGE_B)        /* 98304 */
#define SMEM_SZ (BIAS_OFF + 512)
#define NITER   8

__global__ void __launch_bounds__(256, 2) gemm_mma(
    const float* __restrict__ bias, float* __restrict__ out_io)
{
    extern __shared__ char smem[];
    const uint32_t sb0 = smem_u32(smem);
    const int tid = threadIdx.x, wid = tid >> 5, lane = tid & 31;
    const int bn = blockIdx.x * 128, bm = blockIdx.y * 128;

    if (tid < 128) ((float*)(smem + BIAS_OFF))[tid] = bias[bn + tid];

    float acc[2][8][4];
#pragma unroll
    for (int i = 0; i < 2; i++)
#pragma unroll
        for (int j = 0; j < 8; j++)
#pragma unroll
            for (int q = 0; q < 4; q++) acc[i][j][q] = 0.0f;

    /* per k-chunk: load A|B tiles (128x64 fp16 each), 8 cp16/thread */
    auto load_stage = [&](int c, int s) {
        const int ko = c * 64;
        const __half* srcA = g_Ah + (size_t)bm * INDIM + ko;
        const __half* srcB = g_Wh + (size_t)bn * INDIM + ko;
        const uint32_t dst = sb0 + s * STAGE_B;
#pragma unroll
        for (int j = 0; j < 8; j++) {
            const int id = tid + 256 * j;          /* 0..2047 */
            const int t = id >> 10;                /* 0: A, 1: B */
            const int w = id & 1023;
            const int row = w >> 3, un = w & 7;
            const int sw = un ^ (row & 7);
            const __half* src = t ? srcB : srcA;
            cp16(dst + t * TILE_B + row * ROWB + sw * 16,
                 src + (size_t)row * INDIM + un * 8);
        }
    };

    load_stage(0, 0); CP_COMMIT();
    load_stage(1, 1); CP_COMMIT();

    const int wm = (wid & 3) * 32;     /* 4 warps down m   */
    const int wn = (wid >> 2) * 64;    /* 2 warps across n */
    const int lr = lane & 15;          /* row within 16    */
    const int cb = lane >> 4;          /* 16B chunk base   */
    const int lx = lr & 7;             /* swizzle key      */

    auto fragaddr = [&](uint32_t tilebase, int rowoff, int ks) -> uint32_t {
        return tilebase + (rowoff + lr) * ROWB + (((cb + 2 * ks) ^ lx) * 16);
    };

    for (int it = 0; it < NITER; it++) {
        const int s = it % NSTG;
        CP_WAIT1();
        __syncthreads();

        const uint32_t aB = sb0 + s * STAGE_B;
        const uint32_t bB = aB + TILE_B;

#pragma unroll
        for (int ks = 0; ks < 4; ks++) {
            uint32_t a[2][4], bq[4][4];
            ldsm4(a[0], fragaddr(aB, wm, ks));
            ldsm4(a[1], fragaddr(aB, wm + 16, ks));
#pragma unroll
            for (int pr = 0; pr < 4; pr++)
                ldsm4(bq[pr], fragaddr(bB, wn + pr * 16, ks));
#pragma unroll
            for (int mt = 0; mt < 2; mt++)
#pragma unroll
                for (int nt = 0; nt < 8; nt++)
                    mma16816(acc[mt][nt], a[mt],
                             bq[nt >> 1][nt & 1], bq[nt >> 1][(nt & 1) + 2]);
        }
        if (it + 2 < NITER) load_stage(it + 2, (it + 2) % NSTG);
        CP_COMMIT();                    /* unconditional: group numbering */
    }
    __syncthreads();

    /* epilogue: +bias, optional tanh (soma_bias half), float2 stores */
    const float* bsh = (const float*)(smem + BIAS_OFF);
    const bool is_sb = (bn < MEM);
    float* ob = is_sb ? g_sb : out_io;
    const int cs = is_sb ? bn : (bn - MEM);

#pragma unroll
    for (int mt = 0; mt < 2; mt++) {
        const int r0 = bm + wm + mt * 16 + (lane >> 2);
#pragma unroll
        for (int nt = 0; nt < 8; nt++) {
            const int col = wn + nt * 8 + (lane & 3) * 2;
            const float b0 = bsh[col], b1 = bsh[col + 1];
            float2 v0, v1;
            v0.x = acc[mt][nt][0] + b0; v0.y = acc[mt][nt][1] + b1;
            v1.x = acc[mt][nt][2] + b0; v1.y = acc[mt][nt][3] + b1;
            if (is_sb) {
                v0.x = 5.0f * tanhf(v0.x * 0.2f); v0.y = 5.0f * tanhf(v0.y * 0.2f);
                v1.x = 5.0f * tanhf(v1.x * 0.2f); v1.y = 5.0f * tanhf(v1.y * 0.2f);
            }
            *(float2*)&ob[(size_t)r0 * MEM + cs + col] = v0;
            *(float2*)&ob[(size_t)(r0 + 8) * MEM + cs + col] = v1;
        }
    }
}

/* --------------- fp32 -> fp16 convert (u and W in one launch) ------------ */
#define NA (MROWS * INDIM / 4)   /* 8388608 float4 elems of u */
#define NW (NCOLS * INDIM / 4)   /* 262144  float4 elems of W */

__device__ __forceinline__ void cvt4(const float4 v, __half2* dst2, size_t i) {
    dst2[2 * i]     = __floats2half2_rn(v.x, v.y);
    dst2[2 * i + 1] = __floats2half2_rn(v.z, v.w);
}

__global__ void __launch_bounds__(256) cvt_all(const float* __restrict__ u,
                                               const float* __restrict__ W) {
    const size_t i = (size_t)blockIdx.x * 256 + threadIdx.x;
    if (i < NA) {
        float4 v = ((const float4*)u)[i];
        cvt4(v, (__half2*)g_Ah, i);
    } else {
        const size_t j = i - NA;
        float4 v = ((const float4*)W)[j];
        cvt4(v, (__half2*)g_Wh, j);
    }
}

/* ------------- sequential scan: 1 thread/lane, pf=4 (occ 2x) ------------- */
__device__ __forceinline__ void step1(float& hf, float& hs, float io, float sb) {
    const float d = hs + 0.4f;
    const float hfn = tanhf(io + 4.0f * hf - 7.0f * d * d + sb);
    const float e = __expf(-10.0f * (hf - 0.5f));
    const float eps = 0.9f + __fdividef(0.9f, 1.0f + e);
    hs += eps * (hf - hs);
    hf = hfn;
}

__global__ void __launch_bounds__(128) scan1(const float* __restrict__ h0,
                                             float* __restrict__ out) {
    const int g = blockIdx.x * 128 + threadIdx.x;  /* 0..131071 */
    const int b = g >> 10;
    const int m = g & 1023;

    float hf = h0[(size_t)b * MEM + m];
    float hs = h0[(size_t)BATCH * MEM + (size_t)b * MEM + m];

    size_t idx = (size_t)b * LSEQ * MEM + m;

    float io[4], sb[4];
#pragma unroll
    for (int k = 0; k < 4; k++) {
        io[k] = out[idx + (size_t)k * MEM];
        sb[k] = g_sb[idx + (size_t)k * MEM];
    }

#pragma unroll 1
    for (int t = 0; t < LSEQ; t += 4) {
        float nio[4], nsb[4];
        if (t + 4 < LSEQ) {
#pragma unroll
            for (int k = 0; k < 4; k++) {
                nio[k] = out[idx + (size_t)(k + 4) * MEM];
                nsb[k] = g_sb[idx + (size_t)(k + 4) * MEM];
            }
        }
#pragma unroll
        for (int k = 0; k < 4; k++) {
            step1(hf, hs, io[k], sb[k]);
            out[idx] = hf;
            idx += MEM;
        }
        if (t + 4 < LSEQ) {
#pragma unroll
            for (int k = 0; k < 4; k++) { io[k] = nio[k]; sb[k] = nsb[k]; }
        }
    }
    out[(size_t)MROWS * MEM + (size_t)b * MEM + m] = hf;  /* hf_last */
}

/* ------------------------------- launch ---------------------------------- */
extern "C" void kernel_launch(void* const* d_in, const int* in_sizes, int n_in,
                              void* d_out, int out_size)
{
    const float* u    = (const float*)d_in[0];  /* [128,512,512] */
    const float* h0   = (const float*)d_in[1];  /* [2,128,1024]  */
    const float* W    = (const float*)d_in[2];  /* [2048,512]    */
    const float* bias = (const float*)d_in[3];  /* [2048]        */
    float* out = (float*)d_out;

    cudaFuncSetAttribute(gemm_mma, cudaFuncAttributeMaxDynamicSharedMemorySize, SMEM_SZ);

    cvt_all<<<(NA + NW) / 256, 256>>>(u, W);
    gemm_mma<<<dim3(NCOLS / 128, MROWS / 128), 256, SMEM_SZ>>>(bias, out);
    scan1<<<(BATCH * MEM) / 128, 128>>>(h0, out);
}

// round 15
// speedup vs baseline: 1.0176x; 1.0011x over previous
#include <cuda_runtime.h>
#include <cuda_fp16.h>
#include <cstdint>
#include <math.h>

#define MEM   1024
#define LSEQ  512
#define BATCH 128
#define INDIM 512
#define MROWS (BATCH * LSEQ)   /* 65536 */
#define NCOLS (2 * MEM)        /* 2048  */

/* ---- static scratch (no runtime allocation) ------------------------------ */
__device__ __align__(128) __half g_Ah[(size_t)MROWS * INDIM];
__device__ __align__(128) __half g_Wh[(size_t)NCOLS * INDIM];
__device__ __align__(128) float  g_sb[(size_t)MROWS * MEM];   /* soma_bias */

/* ------------------------------ PTX helpers ------------------------------ */
__device__ __forceinline__ uint32_t smem_u32(const void* p) {
    uint32_t a;
    asm("{ .reg .u64 t; cvta.to.shared.u64 t, %1; cvt.u32.u64 %0, t; }"
        : "=r"(a) : "l"(p));
    return a;
}
__device__ __forceinline__ void cp16(uint32_t dst, const void* src) {
    asm volatile("cp.async.cg.shared.global [%0], [%1], 16;" :: "r"(dst), "l"(src));
}
#define CP_COMMIT() asm volatile("cp.async.commit_group;" ::: "memory")
#define CP_WAIT1()  asm volatile("cp.async.wait_group 1;" ::: "memory")

__device__ __forceinline__ void ldsm4(uint32_t* r, uint32_t addr) {
    asm volatile("ldmatrix.sync.aligned.m8n8.x4.shared.b16 {%0,%1,%2,%3}, [%4];"
                 : "=r"(r[0]), "=r"(r[1]), "=r"(r[2]), "=r"(r[3]) : "r"(addr));
}
__device__ __forceinline__ void mma16816(float* c, const uint32_t* a,
                                         const uint32_t b0, const uint32_t b1) {
    asm volatile(
        "mma.sync.aligned.m16n8k16.row.col.f32.f16.f16.f32 "
        "{%0,%1,%2,%3}, {%4,%5,%6,%7}, {%8,%9}, {%0,%1,%2,%3};"
        : "+f"(c[0]), "+f"(c[1]), "+f"(c[2]), "+f"(c[3])
        : "r"(a[0]), "r"(a[1]), "r"(a[2]), "r"(a[3]), "r"(b0), "r"(b1));
}

/* --------------- GEMM via mma.sync, single-pass fp16 --------------------- */
/* CTA 128x128, warp 32x64 (4m x 2n), BK=64, 8 k-chunks, 2 CTAs/SM          */
/* smem tile: 128 rows x 128B, XOR-16B swizzle: chunk' = chunk ^ (row & 7)   */
#define ROWB    128
#define TILE_B  (128 * ROWB)             /* 16384                            */
#define STAGE_B (2 * TILE_B)             /* A | B = 32768                    */
#define NSTG    3
#define BIAS_OFF (NSTG * STAGE_B)        /* 98304 */
#define SMEM_SZ (BIAS_OFF + 512)
#define NITER   8

__global__ void __launch_bounds__(256, 2) gemm_mma(
    const float* __restrict__ bias, float* __restrict__ out_io)
{
    extern __shared__ char smem[];
    const uint32_t sb0 = smem_u32(smem);
    const int tid = threadIdx.x, wid = tid >> 5, lane = tid & 31;
    const int bn = blockIdx.x * 128, bm = blockIdx.y * 128;

    if (tid < 128) ((float*)(smem + BIAS_OFF))[tid] = bias[bn + tid];

    float acc[2][8][4];
#pragma unroll
    for (int i = 0; i < 2; i++)
#pragma unroll
        for (int j = 0; j < 8; j++)
#pragma unroll
            for (int q = 0; q < 4; q++) acc[i][j][q] = 0.0f;

    /* per k-chunk: load A|B tiles (128x64 fp16 each), 8 cp16/thread */
    auto load_stage = [&](int c, int s) {
        const int ko = c * 64;
        const __half* srcA = g_Ah + (size_t)bm * INDIM + ko;
        const __half* srcB = g_Wh + (size_t)bn * INDIM + ko;
        const uint32_t dst = sb0 + s * STAGE_B;
#pragma unroll
        for (int j = 0; j < 8; j++) {
            const int id = tid + 256 * j;          /* 0..2047 */
            const int t = id >> 10;                /* 0: A, 1: B */
            const int w = id & 1023;
            const int row = w >> 3, un = w & 7;
            const int sw = un ^ (row & 7);
            const __half* src = t ? srcB : srcA;
            cp16(dst + t * TILE_B + row * ROWB + sw * 16,
                 src + (size_t)row * INDIM + un * 8);
        }
    };

    load_stage(0, 0); CP_COMMIT();
    load_stage(1, 1); CP_COMMIT();

    const int wm = (wid & 3) * 32;     /* 4 warps down m   */
    const int wn = (wid >> 2) * 64;    /* 2 warps across n */
    const int lr = lane & 15;          /* row within 16    */
    const int cb = lane >> 4;          /* 16B chunk base   */
    const int lx = lr & 7;             /* swizzle key      */

    auto fragaddr = [&](uint32_t tilebase, int rowoff, int ks) -> uint32_t {
        return tilebase + (rowoff + lr) * ROWB + (((cb + 2 * ks) ^ lx) * 16);
    };

    for (int it = 0; it < NITER; it++) {
        const int s = it % NSTG;
        CP_WAIT1();
        __syncthreads();

        const uint32_t aB = sb0 + s * STAGE_B;
        const uint32_t bB = aB + TILE_B;

#pragma unroll
        for (int ks = 0; ks < 4; ks++) {
            uint32_t a[2][4], bq[4][4];
            ldsm4(a[0], fragaddr(aB, wm, ks));
            ldsm4(a[1], fragaddr(aB, wm + 16, ks));
#pragma unroll
            for (int pr = 0; pr < 4; pr++)
                ldsm4(bq[pr], fragaddr(bB, wn + pr * 16, ks));
#pragma unroll
            for (int mt = 0; mt < 2; mt++)
#pragma unroll
                for (int nt = 0; nt < 8; nt++)
                    mma16816(acc[mt][nt], a[mt],
                             bq[nt >> 1][nt & 1], bq[nt >> 1][(nt & 1) + 2]);
        }
        if (it + 2 < NITER) load_stage(it + 2, (it + 2) % NSTG);
        CP_COMMIT();                    /* unconditional: group numbering */
    }
    __syncthreads();

    /* epilogue: +bias, optional tanh (soma_bias half), float2 stores */
    const float* bsh = (const float*)(smem + BIAS_OFF);
    const bool is_sb = (bn < MEM);
    float* ob = is_sb ? g_sb : out_io;
    const int cs = is_sb ? bn : (bn - MEM);

#pragma unroll
    for (int mt = 0; mt < 2; mt++) {
        const int r0 = bm + wm + mt * 16 + (lane >> 2);
#pragma unroll
        for (int nt = 0; nt < 8; nt++) {
            const int col = wn + nt * 8 + (lane & 3) * 2;
            const float b0 = bsh[col], b1 = bsh[col + 1];
            float2 v0, v1;
            v0.x = acc[mt][nt][0] + b0; v0.y = acc[mt][nt][1] + b1;
            v1.x = acc[mt][nt][2] + b0; v1.y = acc[mt][nt][3] + b1;
            if (is_sb) {
                v0.x = 5.0f * tanhf(v0.x * 0.2f); v0.y = 5.0f * tanhf(v0.y * 0.2f);
                v1.x = 5.0f * tanhf(v1.x * 0.2f); v1.y = 5.0f * tanhf(v1.y * 0.2f);
            }
            *(float2*)&ob[(size_t)r0 * MEM + cs + col] = v0;
            *(float2*)&ob[(size_t)(r0 + 8) * MEM + cs + col] = v1;
        }
    }
}

/* --------------- fp32 -> fp16 convert (u and W in one launch) ------------ */
#define NA (MROWS * INDIM / 4)   /* 8388608 float4 elems of u */
#define NW (NCOLS * INDIM / 4)   /* 262144  float4 elems of W */

__device__ __forceinline__ void cvt4(const float4 v, __half2* dst2, size_t i) {
    dst2[2 * i]     = __floats2half2_rn(v.x, v.y);
    dst2[2 * i + 1] = __floats2half2_rn(v.z, v.w);
}

__global__ void __launch_bounds__(256) cvt_all(const float* __restrict__ u,
                                               const float* __restrict__ W) {
    const size_t i = (size_t)blockIdx.x * 256 + threadIdx.x;
    if (i < NA) {
        float4 v = ((const float4*)u)[i];
        cvt4(v, (__half2*)g_Ah, i);
    } else {
        const size_t j = i - NA;
        float4 v = ((const float4*)W)[j];
        cvt4(v, (__half2*)g_Wh, j);
    }
}

/* ------------- sequential scan: 1 thread/lane, pf=4, fast tanh ----------- */
/* tanh(x) = 1 - 2/(e^{2x}+1): MUFU.EX2 + MUFU.RCP (~1e-6 abs err), vs the  */
/* ~25-instruction precise tanhf polynomial. Scan is issue-bound: this cuts */
/* per-step instructions ~2x.                                               */
__device__ __forceinline__ float fast_tanh(float x) {
    const float e = __expf(2.0f * x);
    return 1.0f - __fdividef(2.0f, e + 1.0f);
}

__device__ __forceinline__ void step1(float& hf, float& hs, float io, float sb) {
    const float d = hs + 0.4f;
    const float hfn = fast_tanh(io + 4.0f * hf - 7.0f * d * d + sb);
    const float e = __expf(-10.0f * (hf - 0.5f));
    const float eps = 0.9f + __fdividef(0.9f, 1.0f + e);
    hs += eps * (hf - hs);
    hf = hfn;
}

__global__ void __launch_bounds__(128) scan1(const float* __restrict__ h0,
                                             float* __restrict__ out) {
    const int g = blockIdx.x * 128 + threadIdx.x;  /* 0..131071 */
    const int b = g >> 10;
    const int m = g & 1023;

    float hf = h0[(size_t)b * MEM + m];
    float hs = h0[(size_t)BATCH * MEM + (size_t)b * MEM + m];

    size_t idx = (size_t)b * LSEQ * MEM + m;

    float io[4], sb[4];
#pragma unroll
    for (int k = 0; k < 4; k++) {
        io[k] = out[idx + (size_t)k * MEM];
        sb[k] = g_sb[idx + (size_t)k * MEM];
    }

#pragma unroll 1
    for (int t = 0; t < LSEQ; t += 4) {
        float nio[4], nsb[4];
        if (t + 4 < LSEQ) {
#pragma unroll
            for (int k = 0; k < 4; k++) {
                nio[k] = out[idx + (size_t)(k + 4) * MEM];
                nsb[k] = g_sb[idx + (size_t)(k + 4) * MEM];
            }
        }
#pragma unroll
        for (int k = 0; k < 4; k++) {
            step1(hf, hs, io[k], sb[k]);
            out[idx] = hf;
            idx += MEM;
        }
        if (t + 4 < LSEQ) {
#pragma unroll
            for (int k = 0; k < 4; k++) { io[k] = nio[k]; sb[k] = nsb[k]; }
        }
    }
    out[(size_t)MROWS * MEM + (size_t)b * MEM + m] = hf;  /* hf_last */
}

/* ------------------------------- launch ---------------------------------- */
extern "C" void kernel_launch(void* const* d_in, const int* in_sizes, int n_in,
                              void* d_out, int out_size)
{
    const float* u    = (const float*)d_in[0];  /* [128,512,512] */
    const float* h0   = (const float*)d_in[1];  /* [2,128,1024]  */
    const float* W    = (const float*)d_in[2];  /* [2048,512]    */
    const float* bias = (const float*)d_in[3];  /* [2048]        */
    float* out = (float*)d_out;

    cudaFuncSetAttribute(gemm_mma, cudaFuncAttributeMaxDynamicSharedMemorySize, SMEM_SZ);

    cvt_all<<<(NA + NW) / 256, 256>>>(u, W);
    gemm_mma<<<dim3(NCOLS / 128, MROWS / 128), 256, SMEM_SZ>>>(bias, out);
    scan1<<<(BATCH * MEM) / 128, 128>>>(h0, out);
}